// round 10
// baseline (speedup 1.0000x reference)
#include <cuda_runtime.h>
#include <cuda_bf16.h>
#include <cstdint>
#include <cstddef>

// Problem constants
#define B_  32
#define S_  2048
#define F_  512
#define MOMENTUM 0.1f
#define EPS 1e-5f

typedef __nv_bfloat16 bf16;

// ---------------- device scratch (static, no allocations) ----------------
// All GEMM operands stored as bf16 hi/lo pairs, K-columns stored in
// MMA-fragment-permuted order (within each 16-column group).
__device__ bf16  g_xnh [(size_t)B_ * S_ * F_];   // xn, perm feature cols
__device__ bf16  g_xnl [(size_t)B_ * S_ * F_];
__device__ bf16  g_xTh [(size_t)B_ * F_ * S_];   // xn^T, perm seq cols
__device__ bf16  g_xTl [(size_t)B_ * F_ * S_];
__device__ float g_sig [(size_t)B_ * F_ * F_];   // sigma fp32 (logical cols)
__device__ bf16  g_sigh[(size_t)B_ * F_ * F_];   // sigma hi/lo (perm cols)
__device__ bf16  g_sigl[(size_t)B_ * F_ * F_];
__device__ bf16  g_Ph  [(size_t)B_ * F_ * F_];
__device__ bf16  g_Pl  [(size_t)B_ * F_ * F_];
__device__ bf16  g_Qh  [(size_t)B_ * F_ * F_];
__device__ bf16  g_Ql  [(size_t)B_ * F_ * F_];
__device__ bf16  g_T1h [(size_t)B_ * F_ * F_];
__device__ bf16  g_T1l [(size_t)B_ * F_ * F_];
__device__ bf16  g_T2h [(size_t)B_ * F_ * F_];
__device__ bf16  g_T2l [(size_t)B_ * F_ * F_];
__device__ float g_mean [B_ * F_];
__device__ float g_invtr[B_];
__device__ float g_rstr [B_];

// fragment-order permutation of a logical column index (within 16-groups)
__device__ __forceinline__ int permc(int c) {
    int g = c & 15, base = c & ~15;
    int slot = (g < 8) ? (((g >> 1) << 2) | (g & 1))
                       : ((((g - 8) >> 1) << 2) | 2 | (g & 1));
    return base | slot;
}

__device__ __forceinline__ void split_bf16(float x, bf16& h, bf16& l) {
    h = __float2bfloat16_rn(x);
    l = __float2bfloat16_rn(x - __bfloat162float(h));
}

// ---------------- elementwise kernels ----------------
__global__ void mean_kernel(const float* __restrict__ x,
                            const float* __restrict__ rm,
                            float* __restrict__ mean) {
    int b = blockIdx.x;
    int f = threadIdx.x;
    const float* xb = x + (size_t)b * S_ * F_ + f;
    float acc = 0.f;
    #pragma unroll 8
    for (int s = 0; s < S_; s++) acc += xb[(size_t)s * F_];
    mean[b * F_ + f] = (1.f - MOMENTUM) * rm[f] + MOMENTUM * (acc * (1.f / (float)S_));
}

// center, split, write xn (perm f cols) and xn^T (perm s cols)
__global__ void ct_kernel(const float* __restrict__ x,
                          const float* __restrict__ mean,
                          bf16* __restrict__ xnh, bf16* __restrict__ xnl,
                          bf16* __restrict__ xTh, bf16* __restrict__ xTl) {
    __shared__ float t[32][33];
    int b = blockIdx.z;
    int s0 = blockIdx.x * 32, f0 = blockIdx.y * 32;
    int tx = threadIdx.x, ty = threadIdx.y;
    float m = mean[b * F_ + f0 + tx];
    const float* xb = x + (size_t)b * S_ * F_;
    size_t bo = (size_t)b * S_ * F_;
    int pf = f0 + permc(tx);
    #pragma unroll
    for (int i = 0; i < 4; i++) {
        int s = s0 + ty + i * 8;
        float v = xb[(size_t)s * F_ + f0 + tx] - m;
        t[ty + i * 8][tx] = v;
        bf16 h, l;
        split_bf16(v, h, l);
        xnh[bo + (size_t)s * F_ + pf] = h;
        xnl[bo + (size_t)s * F_ + pf] = l;
    }
    __syncthreads();
    size_t bt = (size_t)b * F_ * S_;
    int ps = s0 + permc(tx);
    #pragma unroll
    for (int i = 0; i < 4; i++) {
        int f = f0 + ty + i * 8;
        float v = t[tx][ty + i * 8];
        bf16 h, l;
        split_bf16(v, h, l);
        xTh[bt + (size_t)f * S_ + ps] = h;
        xTl[bt + (size_t)f * S_ + ps] = l;
    }
}

__global__ void trace_kernel(const float* __restrict__ sigma,
                             float* __restrict__ invtr,
                             float* __restrict__ rstr) {
    __shared__ float red[512];
    int b = blockIdx.x, t = threadIdx.x;
    red[t] = sigma[(size_t)b * F_ * F_ + (size_t)t * (F_ + 1)];
    __syncthreads();
    for (int s = 256; s > 0; s >>= 1) {
        if (t < s) red[t] += red[t + s];
        __syncthreads();
    }
    if (t == 0) {
        float tr = red[0];
        invtr[b] = 1.f / tr;
        rstr[b]  = 1.f / sqrtf(tr);
    }
}

// P1 = 1.5I - 0.5 sigma/tr, written as hi/lo with permuted cols
__global__ void initp_kernel(const float* __restrict__ sigma,
                             const float* __restrict__ invtr,
                             bf16* __restrict__ Ph, bf16* __restrict__ Pl) {
    size_t idx = (size_t)blockIdx.x * blockDim.x + threadIdx.x;
    int b = (int)(idx >> 18);
    int r = (int)((idx >> 9) & (F_ - 1));
    int c = (int)(idx & (F_ - 1));
    float v = -0.5f * invtr[b] * sigma[idx];
    if (r == c) v += 1.5f;
    bf16 h, l;
    split_bf16(v, h, l);
    size_t o = ((idx & ~(size_t)511)) | (size_t)permc(c);
    Ph[o] = h;
    Pl[o] = l;
}

// ---------------- helpers ----------------
__device__ __forceinline__ void cp_async16(void* smem_dst, const void* gmem_src) {
    uint32_t s = (uint32_t)__cvta_generic_to_shared(smem_dst);
    asm volatile("cp.async.cg.shared.global [%0], [%1], 16;\n" :: "r"(s), "l"(gmem_src));
}
#define CP_COMMIT asm volatile("cp.async.commit_group;" ::: "memory")
#define CP_WAIT1  asm volatile("cp.async.wait_group 1;"  ::: "memory")
#define CP_WAIT0  asm volatile("cp.async.wait_group 0;"  ::: "memory")

__device__ __forceinline__ void mma_bf16(float* c, const uint32_t* a, const uint32_t* b) {
    asm volatile(
        "mma.sync.aligned.m16n8k16.row.col.f32.bf16.bf16.f32 "
        "{%0,%1,%2,%3}, {%4,%5,%6,%7}, {%8,%9}, {%0,%1,%2,%3};"
        : "+f"(c[0]), "+f"(c[1]), "+f"(c[2]), "+f"(c[3])
        : "r"(a[0]), "r"(a[1]), "r"(a[2]), "r"(a[3]), "r"(b[0]), "r"(b[1]));
}

// ---------------- bf16x3 GEMM, pre-split operands ----------------
// C = A * B^T with both operands row-major, K along (permuted) columns.
// All symmetric-B uses rely on B^T = B. N = F_ = 512 always.
// mode 0: C = AB            (write hi/lo)
// mode 1: C = 1.5*D - 0.5*scale[b]*AB   (D = hi/lo reconstruct; write hi/lo)
// mode 2: C = scale[b]*AB   (write fp32 logical)
// mode 3: C = 0.9*E + 0.1*(AB/(S-1)+eps*I)  (write fp32 logical + hi/lo)
// smem per stage: Ah/Al/Bh/Bl each [128][40] bf16 (10240 B) -> 40960 B; x2.
#define STREAM_B 10240
#define STAGE_B  40960
#define GEMM_SMEM_TOTAL (2 * STAGE_B)

template<int TRI>
__global__ __launch_bounds__(256, 2) void gemm_bf16_kernel(
        const bf16* __restrict__ Agh, const bf16* __restrict__ Agl,
        const bf16* __restrict__ Bgh, const bf16* __restrict__ Bgl,
        float* __restrict__ Cf,
        bf16* __restrict__ Cgh, bf16* __restrict__ Cgl,
        const bf16* __restrict__ Dgh, const bf16* __restrict__ Dgl,
        const float* __restrict__ Ef, const float* __restrict__ scale,
        int K, int mode, size_t sAb, size_t sBb, size_t sCb) {
    extern __shared__ char smem[];

    int bz = blockIdx.z;
    const bf16* Ah = Agh + (size_t)bz * sAb;
    const bf16* Al = Agl + (size_t)bz * sAb;
    const bf16* Bh = Bgh + (size_t)bz * sBb;
    const bf16* Bl = Bgl + (size_t)bz * sBb;

    int m0, n0;
    bool mirror = false;
    if (TRI) {
        int t = blockIdx.x;   // 0..9
        int bi = (t < 4) ? 0 : (t < 7) ? 1 : (t < 9) ? 2 : 3;
        int start = (bi == 0) ? 0 : (bi == 1) ? 4 : (bi == 2) ? 7 : 9;
        int bj = bi + (t - start);
        m0 = bi * 128; n0 = bj * 128;
        mirror = (bi != bj);
    } else {
        m0 = blockIdx.y * 128;
        n0 = blockIdx.x * 128;
    }

    int tid  = threadIdx.x;
    int lane = tid & 31;
    int wid  = tid >> 5;
    int warp_m = (wid >> 2) * 64;     // 0 or 64
    int warp_n = (wid & 3) * 32;      // 0,32,64,96
    int g  = lane >> 2;               // 0..7
    int tg = lane & 3;                // 0..3

    float acc[4][4][4];
    #pragma unroll
    for (int i = 0; i < 4; i++)
        #pragma unroll
        for (int j = 0; j < 4; j++)
            #pragma unroll
            for (int q = 0; q < 4; q++) acc[i][j][q] = 0.f;

    // ---- cp.async staging: 4 streams x 2 chunks of 16B per thread ----
    const bf16* gsrc[4] = { Ah + (size_t)m0 * K, Al + (size_t)m0 * K,
                            Bh + (size_t)n0 * K, Bl + (size_t)n0 * K };
    auto prefetch = [&](int st, int k0) {
        char* base = smem + st * STAGE_B;
        #pragma unroll
        for (int sm = 0; sm < 4; sm++) {
            #pragma unroll
            for (int q = 0; q < 2; q++) {
                int ch = tid * 2 + q;       // 0..511
                int row = ch >> 2;
                int o = ch & 3;
                cp_async16(base + sm * STREAM_B + row * 80 + o * 16,
                           gsrc[sm] + (size_t)row * K + k0 + o * 8);
            }
        }
    };

    prefetch(0, 0);
    CP_COMMIT;

    const int NC = K >> 5;
    for (int c = 0; c < NC; c++) {
        int bsel = c & 1;
        if (c + 1 < NC) {
            prefetch(bsel ^ 1, (c + 1) * 32);
            CP_COMMIT;
            CP_WAIT1;
        } else {
            CP_WAIT0;
        }
        __syncthreads();

        const char* st = smem + bsel * STAGE_B;
        const char* sAh = st;
        const char* sAl = st + STREAM_B;
        const char* sBh = st + 2 * STREAM_B;
        const char* sBl = st + 3 * STREAM_B;

        #pragma unroll
        for (int kk = 0; kk < 32; kk += 16) {
            int ko = (kk + tg * 4) * 2;        // byte offset of this thread's 4-slot group
            uint2 bh[4], bl[4];
            #pragma unroll
            for (int j = 0; j < 4; j++) {
                int col = warp_n + j * 8 + g;
                bh[j] = *(const uint2*)(sBh + col * 80 + ko);
                bl[j] = *(const uint2*)(sBl + col * 80 + ko);
            }
            #pragma unroll
            for (int i = 0; i < 4; i++) {
                int row = warp_m + i * 16;
                uint2 ah0 = *(const uint2*)(sAh + (row + g) * 80 + ko);
                uint2 ah1 = *(const uint2*)(sAh + (row + g + 8) * 80 + ko);
                uint2 al0 = *(const uint2*)(sAl + (row + g) * 80 + ko);
                uint2 al1 = *(const uint2*)(sAl + (row + g + 8) * 80 + ko);
                uint32_t ah[4] = { ah0.x, ah1.x, ah0.y, ah1.y };
                uint32_t al[4] = { al0.x, al1.x, al0.y, al1.y };
                #pragma unroll
                for (int j = 0; j < 4; j++) {
                    uint32_t bhr[2] = { bh[j].x, bh[j].y };
                    uint32_t blr[2] = { bl[j].x, bl[j].y };
                    mma_bf16(acc[i][j], ah, bhr);   // hi*hi
                    mma_bf16(acc[i][j], ah, blr);   // hi*lo
                    mma_bf16(acc[i][j], al, bhr);   // lo*hi
                }
            }
        }
        __syncthreads();
    }

    // ---- epilogue ----
    float sc = 0.f;
    if (mode == 1) sc = -0.5f * scale[bz];
    else if (mode == 2) sc = scale[bz];
    const bf16* Dh = (mode == 1) ? (Dgh + (size_t)bz * sCb) : nullptr;
    const bf16* Dl = (mode == 1) ? (Dgl + (size_t)bz * sCb) : nullptr;
    float* Cfp = (mode >= 2) ? (Cf + (size_t)bz * sCb) : nullptr;
    bf16* Ch = (mode != 2) ? (Cgh + (size_t)bz * sCb) : nullptr;
    bf16* Cl = (mode != 2) ? (Cgl + (size_t)bz * sCb) : nullptr;
    const float inv_nm1 = 1.f / (float)(S_ - 1);

    #pragma unroll
    for (int i = 0; i < 4; i++) {
        #pragma unroll
        for (int j = 0; j < 4; j++) {
            int r0 = m0 + warp_m + i * 16 + g;
            int c0 = n0 + warp_n + j * 8 + 2 * tg;                       // logical
            int sc0 = n0 + warp_n + (j >> 1) * 16 + tg * 4 + (j & 1) * 2; // stored (perm)
            #pragma unroll
            for (int half = 0; half < 2; half++) {
                int r = r0 + half * 8;
                float v0 = acc[i][j][half * 2 + 0];
                float v1 = acc[i][j][half * 2 + 1];
                size_t offS = (size_t)r * F_ + sc0;   // stored cols
                size_t offL = (size_t)r * F_ + c0;    // logical cols
                float o0, o1;
                if (mode == 0) {
                    o0 = v0; o1 = v1;
                } else if (mode == 1) {
                    float d0 = __bfloat162float(Dh[offS]) + __bfloat162float(Dl[offS]);
                    float d1 = __bfloat162float(Dh[offS + 1]) + __bfloat162float(Dl[offS + 1]);
                    o0 = 1.5f * d0 + sc * v0;
                    o1 = 1.5f * d1 + sc * v1;
                } else if (mode == 2) {
                    o0 = sc * v0; o1 = sc * v1;
                } else {
                    float s0 = v0 * inv_nm1 + ((r == c0)     ? EPS : 0.f);
                    float s1 = v1 * inv_nm1 + ((r == c0 + 1) ? EPS : 0.f);
                    o0 = (1.f - MOMENTUM) * Ef[offL] + MOMENTUM * s0;
                    o1 = (1.f - MOMENTUM) * Ef[offL + 1] + MOMENTUM * s1;
                }
                if (mode >= 2) {
                    *(float2*)(Cfp + offL) = make_float2(o0, o1);
                    if (TRI && mirror && mode == 3) {
                        Cfp[(size_t)c0 * F_ + r]       = o0;
                        Cfp[(size_t)(c0 + 1) * F_ + r] = o1;
                    }
                }
                if (mode != 2) {
                    bf16 h0, l0, h1, l1;
                    split_bf16(o0, h0, l0);
                    split_bf16(o1, h1, l1);
                    __nv_bfloat162 hp = __halves2bfloat162(h0, h1);
                    __nv_bfloat162 lp = __halves2bfloat162(l0, l1);
                    *(__nv_bfloat162*)(Ch + offS) = hp;
                    *(__nv_bfloat162*)(Cl + offS) = lp;
                    if (TRI && mirror) {
                        int pr = permc(r);
                        Ch[(size_t)c0 * F_ + pr] = h0;
                        Cl[(size_t)c0 * F_ + pr] = l0;
                        Ch[(size_t)(c0 + 1) * F_ + pr] = h1;
                        Cl[(size_t)(c0 + 1) * F_ + pr] = l1;
                    }
                }
            }
        }
    }
}

// ---------------- host launcher ----------------
extern "C" void kernel_launch(void* const* d_in, const int* in_sizes, int n_in,
                              void* d_out, int out_size) {
    const float* x  = (const float*)d_in[0];
    const float* rm = (const float*)d_in[1];
    const float* rc = (const float*)d_in[2];
    float* out = (float*)d_out;

    bf16 *xnh, *xnl, *xTh, *xTl, *sigh, *sigl, *Ph, *Pl, *Qh, *Ql, *T1h, *T1l, *T2h, *T2l;
    float *sig, *mean, *invtr, *rstr;
    cudaGetSymbolAddress((void**)&xnh,  g_xnh);
    cudaGetSymbolAddress((void**)&xnl,  g_xnl);
    cudaGetSymbolAddress((void**)&xTh,  g_xTh);
    cudaGetSymbolAddress((void**)&xTl,  g_xTl);
    cudaGetSymbolAddress((void**)&sig,  g_sig);
    cudaGetSymbolAddress((void**)&sigh, g_sigh);
    cudaGetSymbolAddress((void**)&sigl, g_sigl);
    cudaGetSymbolAddress((void**)&Ph,   g_Ph);
    cudaGetSymbolAddress((void**)&Pl,   g_Pl);
    cudaGetSymbolAddress((void**)&Qh,   g_Qh);
    cudaGetSymbolAddress((void**)&Ql,   g_Ql);
    cudaGetSymbolAddress((void**)&T1h,  g_T1h);
    cudaGetSymbolAddress((void**)&T1l,  g_T1l);
    cudaGetSymbolAddress((void**)&T2h,  g_T2h);
    cudaGetSymbolAddress((void**)&T2l,  g_T2l);
    cudaGetSymbolAddress((void**)&mean, g_mean);
    cudaGetSymbolAddress((void**)&invtr, g_invtr);
    cudaGetSymbolAddress((void**)&rstr, g_rstr);

    static bool attr_set = false;
    if (!attr_set) {
        cudaFuncSetAttribute(gemm_bf16_kernel<0>,
            cudaFuncAttributeMaxDynamicSharedMemorySize, GEMM_SMEM_TOTAL);
        cudaFuncSetAttribute(gemm_bf16_kernel<1>,
            cudaFuncAttributeMaxDynamicSharedMemorySize, GEMM_SMEM_TOTAL);
        attr_set = true;
    }

    const size_t FF = (size_t)F_ * F_;
    const size_t SF = (size_t)S_ * F_;

    // 1. blended mean
    mean_kernel<<<B_, F_>>>(x, rm, mean);
    // 2. center + split + transpose
    ct_kernel<<<dim3(S_ / 32, F_ / 32, B_), dim3(32, 8)>>>(x, mean, xnh, xnl, xTh, xTl);
    // 3. sigma (SYRK over xn^T, K = S, triangular)
    gemm_bf16_kernel<1><<<dim3(10, 1, B_), 256, GEMM_SMEM_TOTAL>>>(
        xTh, xTl, xTh, xTl, sig, sigh, sigl, nullptr, nullptr, rc, nullptr,
        S_, 3, SF, SF, FF);
    // 4. trace
    trace_kernel<<<B_, F_>>>(sig, invtr, rstr);
    // 5. P1 = 1.5I - 0.5 sigma/tr
    initp_kernel<<<(unsigned)((size_t)B_ * FF / 256), 256>>>(sig, invtr, Ph, Pl);

    // 6. NS iterations 2..4 (all matrices symmetric)
    bf16 *Pih = Ph, *Pil = Pl, *Poh = Qh, *Pol = Ql;
    for (int it = 0; it < 3; it++) {
        gemm_bf16_kernel<1><<<dim3(10, 1, B_), 256, GEMM_SMEM_TOTAL>>>(
            Pih, Pil, Pih, Pil, nullptr, T1h, T1l, nullptr, nullptr, nullptr, nullptr,
            F_, 0, FF, FF, FF);
        gemm_bf16_kernel<1><<<dim3(10, 1, B_), 256, GEMM_SMEM_TOTAL>>>(
            T1h, T1l, Pih, Pil, nullptr, T2h, T2l, nullptr, nullptr, nullptr, nullptr,
            F_, 0, FF, FF, FF);
        gemm_bf16_kernel<1><<<dim3(10, 1, B_), 256, GEMM_SMEM_TOTAL>>>(
            T2h, T2l, sigh, sigl, nullptr, Poh, Pol, Pih, Pil, nullptr, invtr,
            F_, 1, FF, FF, FF);
        bf16* t;
        t = Pih; Pih = Poh; Poh = t;
        t = Pil; Pil = Pol; Pol = t;
    }

    // 7. out = (xn @ P3) * rsqrt(tr)
    gemm_bf16_kernel<0><<<dim3(4, 16, B_), 256, GEMM_SMEM_TOTAL>>>(
        xnh, xnl, Pih, Pil, out, nullptr, nullptr, nullptr, nullptr, nullptr, rstr,
        F_, 2, SF, FF, SF);
}

// round 11
// speedup vs baseline: 1.1451x; 1.1451x over previous
#include <cuda_runtime.h>
#include <cuda_bf16.h>
#include <cstdint>
#include <cstddef>

// Problem constants
#define B_  32
#define S_  2048
#define F_  512
#define MOMENTUM 0.1f
#define EPS 1e-5f

typedef __nv_bfloat16 bf16;

// ---------------- device scratch (static, no allocations) ----------------
__device__ float g_xn   [(size_t)B_ * S_ * F_];   // centered input
__device__ float g_xnT  [(size_t)B_ * F_ * S_];   // transposed (for SYRK)
__device__ float g_sigma[(size_t)B_ * F_ * F_];
__device__ float g_P    [(size_t)B_ * F_ * F_];
__device__ float g_Q    [(size_t)B_ * F_ * F_];
__device__ float g_T1   [(size_t)B_ * F_ * F_];
__device__ float g_T2   [(size_t)B_ * F_ * F_];
__device__ float g_mean [B_ * F_];
__device__ float g_invtr[B_];
__device__ float g_rstr [B_];

// ---------------- elementwise kernels ----------------
__global__ void mean_kernel(const float* __restrict__ x,
                            const float* __restrict__ rm,
                            float* __restrict__ mean) {
    int b = blockIdx.x;
    int f = threadIdx.x;
    const float* xb = x + (size_t)b * S_ * F_ + f;
    float acc = 0.f;
    #pragma unroll 8
    for (int s = 0; s < S_; s++) acc += xb[(size_t)s * F_];
    mean[b * F_ + f] = (1.f - MOMENTUM) * rm[f] + MOMENTUM * (acc * (1.f / (float)S_));
}

// center + write xn and xnT (32x32 smem transpose tiles)
__global__ void ct_kernel(const float* __restrict__ x,
                          const float* __restrict__ mean,
                          float* __restrict__ xn,
                          float* __restrict__ xnT) {
    __shared__ float t[32][33];
    int b = blockIdx.z;
    int s0 = blockIdx.x * 32, f0 = blockIdx.y * 32;
    int tx = threadIdx.x, ty = threadIdx.y;
    float m = mean[b * F_ + f0 + tx];
    const float* xb = x + (size_t)b * S_ * F_;
    float* xnb = xn + (size_t)b * S_ * F_;
    #pragma unroll
    for (int i = 0; i < 4; i++) {
        int s = s0 + ty + i * 8;
        float v = xb[(size_t)s * F_ + f0 + tx] - m;
        xnb[(size_t)s * F_ + f0 + tx] = v;
        t[ty + i * 8][tx] = v;
    }
    __syncthreads();
    float* xtb = xnT + (size_t)b * F_ * S_;
    #pragma unroll
    for (int i = 0; i < 4; i++) {
        int f = f0 + ty + i * 8;
        xtb[(size_t)f * S_ + s0 + tx] = t[tx][ty + i * 8];
    }
}

__global__ void trace_kernel(const float* __restrict__ sigma,
                             float* __restrict__ invtr,
                             float* __restrict__ rstr) {
    __shared__ float red[512];
    int b = blockIdx.x, t = threadIdx.x;
    red[t] = sigma[(size_t)b * F_ * F_ + (size_t)t * (F_ + 1)];
    __syncthreads();
    for (int s = 256; s > 0; s >>= 1) {
        if (t < s) red[t] += red[t + s];
        __syncthreads();
    }
    if (t == 0) {
        float tr = red[0];
        invtr[b] = 1.f / tr;
        rstr[b]  = 1.f / sqrtf(tr);
    }
}

__global__ void initp_kernel(const float* __restrict__ sigma,
                             const float* __restrict__ invtr,
                             float* __restrict__ P) {
    size_t idx = (size_t)blockIdx.x * blockDim.x + threadIdx.x;
    int b = (int)(idx >> 18);
    int r = (int)((idx >> 9) & (F_ - 1));
    int c = (int)(idx & (F_ - 1));
    float v = -0.5f * invtr[b] * sigma[idx];
    if (r == c) v += 1.5f;
    P[idx] = v;
}

// ---------------- helpers ----------------
// split fp32 pair into packed bf16 hi / bf16 lo
__device__ __forceinline__ void split2_bf16(float x, float y, uint32_t& h, uint32_t& l) {
    __nv_bfloat16 hx = __float2bfloat16_rn(x);
    __nv_bfloat16 hy = __float2bfloat16_rn(y);
    float rx = x - __bfloat162float(hx);
    float ry = y - __bfloat162float(hy);
    __nv_bfloat16 lx = __float2bfloat16_rn(rx);
    __nv_bfloat16 ly = __float2bfloat16_rn(ry);
    __nv_bfloat162 hp = __halves2bfloat162(hx, hy);
    __nv_bfloat162 lp = __halves2bfloat162(lx, ly);
    h = *(uint32_t*)&hp;
    l = *(uint32_t*)&lp;
}

__device__ __forceinline__ void mma_bf16(float* c, const uint32_t* a, const uint32_t* b) {
    asm volatile(
        "mma.sync.aligned.m16n8k16.row.col.f32.bf16.bf16.f32 "
        "{%0,%1,%2,%3}, {%4,%5,%6,%7}, {%8,%9}, {%0,%1,%2,%3};"
        : "+f"(c[0]), "+f"(c[1]), "+f"(c[2]), "+f"(c[3])
        : "r"(a[0]), "r"(a[1]), "r"(a[2]), "r"(a[3]), "r"(b[0]), "r"(b[1]));
}

// ---------------- bf16x3 GEMM, register-staged, permuted smem ----------------
// C = A * B^T : A-tile rows m0..m0+127 along K (row stride K), B-tile rows
// n0..n0+127 along K. All B matrices are symmetric (or xnT for SYRK) so this
// computes the desired A@B.
// mode 0: C = AB
// mode 1: C = 1.5*D - 0.5*scale[b]*AB
// mode 2: C = scale[b]*AB
// mode 3: C = 0.9*E + 0.1*(AB/(S-1)+eps*I)   (E has no batch stride)
// smem (single stage, 48 KB): Ah/Al/Bh/Bl each [128 rows][48 bf16] (96 B/row,
// 24 words -> conflict-free uint2 fragment loads). Within each 16-k group the
// uint32 pairs are stored in fragment order: slot s = (u&3)*2 + (u>>2).
#define STREAM_W 3072                    // words per stream (128*24)
#define GEMM_SMEM_TOTAL 49152

template<int TRI>
__global__ __launch_bounds__(256, 2) void gemm_bf16_kernel(
        const float* __restrict__ Ag, const float* __restrict__ Bg,
        float* __restrict__ Cg, const float* __restrict__ Dg,
        const float* __restrict__ Eg, const float* __restrict__ scale,
        int K, int mode, size_t sAb, size_t sBb, size_t sCb) {
    extern __shared__ char smem[];
    uint32_t* sw = (uint32_t*)smem;

    int bz = blockIdx.z;
    const float* A = Ag + (size_t)bz * sAb;
    const float* Bm = Bg + (size_t)bz * sBb;
    float* C = Cg + (size_t)bz * sCb;

    int m0, n0;
    bool mirror = false;
    if (TRI) {
        int t = blockIdx.x;   // 0..9
        int bi = (t < 4) ? 0 : (t < 7) ? 1 : (t < 9) ? 2 : 3;
        int start = (bi == 0) ? 0 : (bi == 1) ? 4 : (bi == 2) ? 7 : 9;
        int bj = bi + (t - start);
        m0 = bi * 128; n0 = bj * 128;
        mirror = (bi != bj);
    } else {
        m0 = blockIdx.y * 128;
        n0 = blockIdx.x * 128;
    }

    int tid  = threadIdx.x;
    int lane = tid & 31;
    int wid  = tid >> 5;
    int warp_m = (wid >> 2) * 64;     // 0 or 64
    int warp_n = (wid & 3) * 32;      // 0,32,64,96
    int g  = lane >> 2;               // 0..7
    int tg = lane & 3;                // 0..3

    float acc[4][4][4];
    #pragma unroll
    for (int i = 0; i < 4; i++)
        #pragma unroll
        for (int j = 0; j < 4; j++)
            #pragma unroll
            for (int q = 0; q < 4; q++) acc[i][j][q] = 0.f;

    // staging mapping: thread -> (row, 16-k half)
    const int mrow = tid >> 1;
    const int half = tid & 1;
    const float* gA = A + (size_t)(m0 + mrow) * K + half * 16;
    const float* gB = Bm + (size_t)(n0 + mrow) * K + half * 16;

    float4 nA[4], nB[4];
    #pragma unroll
    for (int q = 0; q < 4; q++) {
        nA[q] = *(const float4*)(gA + q * 4);
        nB[q] = *(const float4*)(gB + q * 4);
    }

    const int wbase = mrow * 24 + half * 8;   // uint32 index of this thread's group
    const int rot = mrow & 7;
    const int NC = K >> 5;

    for (int c = 0; c < NC; c++) {
        __syncthreads();   // previous mainloop done; smem stage free

        // ---- convert regs -> permuted bf16 hi/lo smem ----
        {
            uint32_t ah[8], al[8], bh[8], bl[8];
            #pragma unroll
            for (int q = 0; q < 4; q++) {
                split2_bf16(nA[q].x, nA[q].y, ah[2 * q],     al[2 * q]);
                split2_bf16(nA[q].z, nA[q].w, ah[2 * q + 1], al[2 * q + 1]);
                split2_bf16(nB[q].x, nB[q].y, bh[2 * q],     bl[2 * q]);
                split2_bf16(nB[q].z, nB[q].w, bh[2 * q + 1], bl[2 * q + 1]);
            }
            #pragma unroll
            for (int it = 0; it < 8; it++) {
                int s = (it + rot) & 7;
                int u = ((s & 1) << 2) | (s >> 1);   // inverse of s=(u&3)*2+(u>>2)
                sw[wbase + s]                = ah[u];
                sw[STREAM_W + wbase + s]     = al[u];
                sw[2 * STREAM_W + wbase + s] = bh[u];
                sw[3 * STREAM_W + wbase + s] = bl[u];
            }
        }
        // issue next chunk's loads (latency hides under mainloop)
        if (c + 1 < NC) {
            const float* pA = gA + (c + 1) * 32;
            const float* pB = gB + (c + 1) * 32;
            #pragma unroll
            for (int q = 0; q < 4; q++) {
                nA[q] = *(const float4*)(pA + q * 4);
                nB[q] = *(const float4*)(pB + q * 4);
            }
        }
        __syncthreads();

        // ---- mainloop: uint2 fragment loads + HMMA ----
        const char* sAh = smem;
        const char* sAl = smem + STREAM_W * 4;
        const char* sBh = smem + 2 * STREAM_W * 4;
        const char* sBl = smem + 3 * STREAM_W * 4;
        #pragma unroll
        for (int kk16 = 0; kk16 < 2; kk16++) {
            int ko = kk16 * 32 + tg * 8;      // byte offset within row
            uint2 bh[4], bl[4];
            #pragma unroll
            for (int j = 0; j < 4; j++) {
                int col = warp_n + j * 8 + g;
                bh[j] = *(const uint2*)(sBh + col * 96 + ko);
                bl[j] = *(const uint2*)(sBl + col * 96 + ko);
            }
            #pragma unroll
            for (int i = 0; i < 4; i++) {
                int row = warp_m + i * 16;
                uint2 h0 = *(const uint2*)(sAh + (row + g) * 96 + ko);
                uint2 h1 = *(const uint2*)(sAh + (row + g + 8) * 96 + ko);
                uint2 l0 = *(const uint2*)(sAl + (row + g) * 96 + ko);
                uint2 l1 = *(const uint2*)(sAl + (row + g + 8) * 96 + ko);
                uint32_t ahf[4] = { h0.x, h1.x, h0.y, h1.y };
                uint32_t alf[4] = { l0.x, l1.x, l0.y, l1.y };
                #pragma unroll
                for (int j = 0; j < 4; j++) {
                    uint32_t bhr[2] = { bh[j].x, bh[j].y };
                    uint32_t blr[2] = { bl[j].x, bl[j].y };
                    mma_bf16(acc[i][j], ahf, bhr);   // hi*hi
                    mma_bf16(acc[i][j], ahf, blr);   // hi*lo
                    mma_bf16(acc[i][j], alf, bhr);   // lo*hi
                }
            }
        }
    }

    // ---- epilogue (fp32, logical layout) ----
    float sc = 0.f;
    if (mode == 1) sc = -0.5f * scale[bz];
    else if (mode == 2) sc = scale[bz];
    const float* D = (mode == 1) ? (Dg + (size_t)bz * sCb) : nullptr;
    const float inv_nm1 = 1.f / (float)(S_ - 1);

    #pragma unroll
    for (int i = 0; i < 4; i++) {
        #pragma unroll
        for (int j = 0; j < 4; j++) {
            int r0 = m0 + warp_m + i * 16 + g;
            int c0 = n0 + warp_n + j * 8 + 2 * tg;
            #pragma unroll
            for (int hh = 0; hh < 2; hh++) {
                int r = r0 + hh * 8;
                float v0 = acc[i][j][hh * 2 + 0];
                float v1 = acc[i][j][hh * 2 + 1];
                size_t off = (size_t)r * F_ + c0;
                float2 o;
                if (mode == 0) {
                    o.x = v0; o.y = v1;
                } else if (mode == 1) {
                    o.x = 1.5f * D[off] + sc * v0;
                    o.y = 1.5f * D[off + 1] + sc * v1;
                } else if (mode == 2) {
                    o.x = sc * v0; o.y = sc * v1;
                } else {
                    float s0 = v0 * inv_nm1 + ((r == c0)     ? EPS : 0.f);
                    float s1 = v1 * inv_nm1 + ((r == c0 + 1) ? EPS : 0.f);
                    o.x = (1.f - MOMENTUM) * Eg[off] + MOMENTUM * s0;
                    o.y = (1.f - MOMENTUM) * Eg[off + 1] + MOMENTUM * s1;
                }
                *(float2*)(C + off) = o;
                if (TRI && mirror) {
                    C[(size_t)c0 * F_ + r]       = o.x;
                    C[(size_t)(c0 + 1) * F_ + r] = o.y;
                }
            }
        }
    }
}

// ---------------- host launcher ----------------
extern "C" void kernel_launch(void* const* d_in, const int* in_sizes, int n_in,
                              void* d_out, int out_size) {
    const float* x  = (const float*)d_in[0];
    const float* rm = (const float*)d_in[1];
    const float* rc = (const float*)d_in[2];
    float* out = (float*)d_out;

    float *xn, *xnT, *sigma, *P, *Q, *T1, *T2, *mean, *invtr, *rstr;
    cudaGetSymbolAddress((void**)&xn,    g_xn);
    cudaGetSymbolAddress((void**)&xnT,   g_xnT);
    cudaGetSymbolAddress((void**)&sigma, g_sigma);
    cudaGetSymbolAddress((void**)&P,     g_P);
    cudaGetSymbolAddress((void**)&Q,     g_Q);
    cudaGetSymbolAddress((void**)&T1,    g_T1);
    cudaGetSymbolAddress((void**)&T2,    g_T2);
    cudaGetSymbolAddress((void**)&mean,  g_mean);
    cudaGetSymbolAddress((void**)&invtr, g_invtr);
    cudaGetSymbolAddress((void**)&rstr,  g_rstr);

    static bool attr_set = false;
    if (!attr_set) {
        cudaFuncSetAttribute(gemm_bf16_kernel<0>,
            cudaFuncAttributeMaxDynamicSharedMemorySize, GEMM_SMEM_TOTAL);
        cudaFuncSetAttribute(gemm_bf16_kernel<1>,
            cudaFuncAttributeMaxDynamicSharedMemorySize, GEMM_SMEM_TOTAL);
        attr_set = true;
    }

    const size_t FF = (size_t)F_ * F_;
    const size_t SF = (size_t)S_ * F_;

    // 1. blended mean
    mean_kernel<<<B_, F_>>>(x, rm, mean);
    // 2. center + transpose (fp32)
    ct_kernel<<<dim3(S_ / 32, F_ / 32, B_), dim3(32, 8)>>>(x, mean, xn, xnT);
    // 3. sigma = 0.9*rc + 0.1*(xnT xnT^T /(S-1) + eps*I)  [triangular]
    gemm_bf16_kernel<1><<<dim3(10, 1, B_), 256, GEMM_SMEM_TOTAL>>>(
        xnT, xnT, sigma, nullptr, rc, nullptr, S_, 3, SF, SF, FF);
    // 4. trace
    trace_kernel<<<B_, F_>>>(sigma, invtr, rstr);
    // 5. P1 = 1.5I - 0.5 sigma/tr
    initp_kernel<<<(unsigned)((size_t)B_ * FF / 256), 256>>>(sigma, invtr, P);

    // 6. NS iterations 2..4 (all matrices symmetric: polynomials in sigma)
    float* Pin = P;
    float* Pout = Q;
    for (int it = 0; it < 3; it++) {
        gemm_bf16_kernel<1><<<dim3(10, 1, B_), 256, GEMM_SMEM_TOTAL>>>(
            Pin, Pin, T1, nullptr, nullptr, nullptr, F_, 0, FF, FF, FF);
        gemm_bf16_kernel<1><<<dim3(10, 1, B_), 256, GEMM_SMEM_TOTAL>>>(
            T1, Pin, T2, nullptr, nullptr, nullptr, F_, 0, FF, FF, FF);
        gemm_bf16_kernel<1><<<dim3(10, 1, B_), 256, GEMM_SMEM_TOTAL>>>(
            T2, sigma, Pout, Pin, nullptr, invtr, F_, 1, FF, FF, FF);
        float* tmp = Pin; Pin = Pout; Pout = tmp;
    }

    // 7. out = (xn @ P3) * rsqrt(tr)   (P3 symmetric)
    gemm_bf16_kernel<0><<<dim3(4, 16, B_), 256, GEMM_SMEM_TOTAL>>>(
        xn, Pin, out, nullptr, nullptr, rstr, F_, 2, SF, FF, SF);
}

// round 12
// speedup vs baseline: 1.1516x; 1.0057x over previous
#include <cuda_runtime.h>
#include <cuda_bf16.h>
#include <cstdint>
#include <cstddef>

// Problem constants
#define B_  32
#define S_  2048
#define F_  512
#define MOMENTUM 0.1f
#define EPS 1e-5f

// ---------------- device scratch (static, no allocations) ----------------
__device__ float g_xn   [(size_t)B_ * S_ * F_];   // 128 MB  centered input
__device__ float g_sigma[(size_t)B_ * F_ * F_];
__device__ float g_P    [(size_t)B_ * F_ * F_];
__device__ float g_Q    [(size_t)B_ * F_ * F_];
__device__ float g_T1   [(size_t)B_ * F_ * F_];
__device__ float g_T2   [(size_t)B_ * F_ * F_];
__device__ float g_mean [B_ * F_];
__device__ float g_invtr[B_];
__device__ float g_rstr [B_];

// ---------------- elementwise kernels ----------------
__global__ void mean_kernel(const float* __restrict__ x,
                            const float* __restrict__ rm,
                            float* __restrict__ mean) {
    int b = blockIdx.x;
    int f = threadIdx.x;
    const float* xb = x + (size_t)b * S_ * F_ + f;
    float acc = 0.f;
    #pragma unroll 8
    for (int s = 0; s < S_; s++) acc += xb[(size_t)s * F_];
    mean[b * F_ + f] = (1.f - MOMENTUM) * rm[f] + MOMENTUM * (acc * (1.f / (float)S_));
}

__global__ void xn_kernel(const float* __restrict__ x,
                          const float* __restrict__ mean,
                          float* __restrict__ xn) {
    size_t p4 = (size_t)blockIdx.x * blockDim.x + threadIdx.x;
    size_t p  = p4 * 4;
    int b = (int)(p >> 20);            // S*F = 2^20
    int f = (int)(p & (F_ - 1));
    float4 xv = *(const float4*)(x + p);
    float4 mv = *(const float4*)(mean + b * F_ + f);
    float4 o;
    o.x = xv.x - mv.x; o.y = xv.y - mv.y; o.z = xv.z - mv.z; o.w = xv.w - mv.w;
    *(float4*)(xn + p) = o;
}

__global__ void trace_kernel(const float* __restrict__ sigma,
                             float* __restrict__ invtr,
                             float* __restrict__ rstr) {
    __shared__ float red[512];
    int b = blockIdx.x, t = threadIdx.x;
    red[t] = sigma[(size_t)b * F_ * F_ + (size_t)t * (F_ + 1)];
    __syncthreads();
    for (int s = 256; s > 0; s >>= 1) {
        if (t < s) red[t] += red[t + s];
        __syncthreads();
    }
    if (t == 0) {
        float tr = red[0];
        invtr[b] = 1.f / tr;
        rstr[b]  = 1.f / sqrtf(tr);
    }
}

__global__ void initp_kernel(const float* __restrict__ sigma,
                             const float* __restrict__ invtr,
                             float* __restrict__ P) {
    size_t idx = (size_t)blockIdx.x * blockDim.x + threadIdx.x;
    int b = (int)(idx >> 18);
    int r = (int)((idx >> 9) & (F_ - 1));
    int c = (int)(idx & (F_ - 1));
    float v = -0.5f * invtr[b] * sigma[idx];
    if (r == c) v += 1.5f;
    P[idx] = v;
}

// ---------------- helpers ----------------
__device__ __forceinline__ void cp_async16(void* smem_dst, const void* gmem_src) {
    uint32_t s = (uint32_t)__cvta_generic_to_shared(smem_dst);
    asm volatile("cp.async.cg.shared.global [%0], [%1], 16;\n" :: "r"(s), "l"(gmem_src));
}
#define CP_COMMIT asm volatile("cp.async.commit_group;" ::: "memory")
#define CP_WAIT1  asm volatile("cp.async.wait_group 1;"  ::: "memory")
#define CP_WAIT0  asm volatile("cp.async.wait_group 0;"  ::: "memory")

// split fp32 pair into packed bf16 hi / bf16 lo (x -> lower 16 bits)
__device__ __forceinline__ void split2_bf16(float x, float y, uint32_t& h, uint32_t& l) {
    __nv_bfloat16 hx = __float2bfloat16_rn(x);
    __nv_bfloat16 hy = __float2bfloat16_rn(y);
    float rx = x - __bfloat162float(hx);
    float ry = y - __bfloat162float(hy);
    __nv_bfloat16 lx = __float2bfloat16_rn(rx);
    __nv_bfloat16 ly = __float2bfloat16_rn(ry);
    __nv_bfloat162 hp = __halves2bfloat162(hx, hy);
    __nv_bfloat162 lp = __halves2bfloat162(lx, ly);
    h = *(uint32_t*)&hp;
    l = *(uint32_t*)&lp;
}

__device__ __forceinline__ void mma_bf16(float* c, const uint32_t* a, const uint32_t* b) {
    asm volatile(
        "mma.sync.aligned.m16n8k16.row.col.f32.bf16.bf16.f32 "
        "{%0,%1,%2,%3}, {%4,%5,%6,%7}, {%8,%9}, {%0,%1,%2,%3};"
        : "+f"(c[0]), "+f"(c[1]), "+f"(c[2]), "+f"(c[3])
        : "r"(a[0]), "r"(a[1]), "r"(a[2]), "r"(a[3]), "r"(b[0]), "r"(b[1]));
}

// ---------------- bf16x3 tensor-core GEMM ----------------
// Identical pipeline to the 1959us kernel (cp.async fp32 double-buffer ->
// convert phase -> mainloop), with ONE change: the bf16 hi/lo smem arrays use
// row stride 48 bf16 (24 words) and fragment-permuted word slots
// (slot s = (u&3)*2 + (u>>2) within each 16-k group), so the mainloop issues
// uint2 (LDS.64) fragment loads -- half the LDS instruction count.
// mode 0: C = AB
// mode 1: C = 1.5*D - 0.5*scale[b]*AB
// mode 2: C = scale[b]*AB
// mode 3: C = 0.9*E + 0.1*(AB/(S-1) + eps*I)   (E has no batch stride)
#define STG_FP32_B 36864
#define OFF_BF     (2 * STG_FP32_B)            // 73728
#define STREAM_W   3072                        // words per bf16 stream (128*24)
#define BF_BUF_B   (4 * STREAM_W * 4)          // 49152
#define GEMM_SMEM_TOTAL (OFF_BF + BF_BUF_B)    // 122880

template<int TRANSA, int TRI>
__global__ __launch_bounds__(256) void gemm_bf16x3_kernel(
        const float* __restrict__ Ag, const float* __restrict__ Bg,
        float* __restrict__ Cg, const float* __restrict__ Dg,
        const float* __restrict__ Eg, const float* __restrict__ scale,
        int M, int N, int K, int mode,
        size_t sAb, size_t sBb, size_t sCb) {
    extern __shared__ char smem[];
    uint32_t* bfw = (uint32_t*)(smem + OFF_BF);

    int bz = blockIdx.z;
    const float* A = Ag + (size_t)bz * sAb;
    const float* Bm = Bg + (size_t)bz * sBb;
    float* C = Cg + (size_t)bz * sCb;

    int m0, n0;
    bool mirror = false;
    if (TRI) {
        int t = blockIdx.x;   // 0..9
        int bi = (t < 4) ? 0 : (t < 7) ? 1 : (t < 9) ? 2 : 3;
        int start = (bi == 0) ? 0 : (bi == 1) ? 4 : (bi == 2) ? 7 : 9;
        int bj = bi + (t - start);
        m0 = bi * 128; n0 = bj * 128;
        mirror = (bi != bj);
    } else {
        m0 = blockIdx.y * 128;
        n0 = blockIdx.x * 128;
    }

    int tid  = threadIdx.x;
    int lane = tid & 31;
    int wid  = tid >> 5;
    int warp_m = (wid >> 2) * 64;     // 0 or 64
    int warp_n = (wid & 3) * 32;      // 0,32,64,96
    int g  = lane >> 2;               // 0..7
    int tg = lane & 3;                // 0..3

    float acc[4][4][4];
    #pragma unroll
    for (int i = 0; i < 4; i++)
        #pragma unroll
        for (int j = 0; j < 4; j++)
            #pragma unroll
            for (int q = 0; q < 4; q++) acc[i][j][q] = 0.f;

    // ---- cp.async staging of fp32 tiles (unchanged from 1959us version) ----
    auto prefetch = [&](int st, int k0) {
        float* sA = (float*)(smem + st * STG_FP32_B);
        float* sB = sA + 4608;
        if (!TRANSA) {
            #pragma unroll
            for (int p = 0; p < 4; p++) {
                int c = tid + p * 256;
                int m = c >> 3;
                int kc = (c & 7) * 4;
                cp_async16(sA + m * 36 + kc, A + (size_t)(m0 + m) * K + k0 + kc);
            }
        } else {
            #pragma unroll
            for (int p = 0; p < 4; p++) {
                int c = tid + p * 256;
                int k = c >> 5;
                int mc = (c & 31) * 4;
                cp_async16(sA + k * 132 + mc, A + (size_t)(k0 + k) * M + m0 + mc);
            }
        }
        #pragma unroll
        for (int p = 0; p < 4; p++) {
            int c = tid + p * 256;
            int k = c >> 5;
            int nc = (c & 31) * 4;
            cp_async16(sB + k * 132 + nc, Bm + (size_t)(k0 + k) * N + n0 + nc);
        }
    };

    prefetch(0, 0);
    CP_COMMIT;

    const int NC = K >> 5;
    const int mrow = tid >> 1;             // 0..127
    const int hg   = tid & 1;              // which 16-k group
    const int ks   = hg * 16;
    const int rot  = mrow & 7;
    const int wb   = mrow * 24 + hg * 8;   // word base in each stream

    for (int c = 0; c < NC; c++) {
        int bsel = c & 1;
        if (c + 1 < NC) {
            prefetch(bsel ^ 1, (c + 1) * 32);
            CP_COMMIT;
            CP_WAIT1;
        } else {
            CP_WAIT0;
        }
        __syncthreads();

        // ---- convert: fp32 stage -> permuted packed bf16 hi/lo ----
        {
            const float* fA = (const float*)(smem + bsel * STG_FP32_B);
            const float* fB = fA + 4608;
            uint32_t ah[8], al[8], bh[8], bl[8];   // logical word index u (k = 2u,2u+1)
            if (!TRANSA) {
                const float* s = fA + mrow * 36 + ks;
                #pragma unroll
                for (int u = 0; u < 4; u++) {
                    float4 v = *(const float4*)(s + 4 * u);
                    split2_bf16(v.x, v.y, ah[2 * u],     al[2 * u]);
                    split2_bf16(v.z, v.w, ah[2 * u + 1], al[2 * u + 1]);
                }
            } else {
                const float* s = fA + mrow;      // [k][132]
                #pragma unroll
                for (int u = 0; u < 8; u++) {
                    float v0 = s[(ks + 2 * u) * 132];
                    float v1 = s[(ks + 2 * u + 1) * 132];
                    split2_bf16(v0, v1, ah[u], al[u]);
                }
            }
            {
                const float* s = fB + mrow;      // [k][132], col = mrow (transpose)
                #pragma unroll
                for (int u = 0; u < 8; u++) {
                    float v0 = s[(ks + 2 * u) * 132];
                    float v1 = s[(ks + 2 * u + 1) * 132];
                    split2_bf16(v0, v1, bh[u], bl[u]);
                }
            }
            // permuted writes: slot s = (u&3)*2 + (u>>2); per-lane rotation
            #pragma unroll
            for (int it = 0; it < 8; it++) {
                int s = (it + rot) & 7;
                int u = ((s & 1) << 2) | (s >> 1);   // inverse of slot mapping
                bfw[wb + s]                = ah[u];
                bfw[STREAM_W + wb + s]     = al[u];
                bfw[2 * STREAM_W + wb + s] = bh[u];
                bfw[3 * STREAM_W + wb + s] = bl[u];
            }
        }
        __syncthreads();

        // ---- mainloop: uint2 fragment loads + HMMA ----
        const char* sAh = (const char*)bfw;
        const char* sAl = sAh + STREAM_W * 4;
        const char* sBh = sAh + 2 * STREAM_W * 4;
        const char* sBl = sAh + 3 * STREAM_W * 4;
        #pragma unroll
        for (int kk16 = 0; kk16 < 2; kk16++) {
            int ko = kk16 * 32 + tg * 8;      // byte offset within 96B row
            uint2 bh[4], bl[4];
            #pragma unroll
            for (int j = 0; j < 4; j++) {
                int col = warp_n + j * 8 + g;
                bh[j] = *(const uint2*)(sBh + col * 96 + ko);
                bl[j] = *(const uint2*)(sBl + col * 96 + ko);
            }
            #pragma unroll
            for (int i = 0; i < 4; i++) {
                int row = warp_m + i * 16;
                uint2 h0 = *(const uint2*)(sAh + (row + g) * 96 + ko);
                uint2 h1 = *(const uint2*)(sAh + (row + g + 8) * 96 + ko);
                uint2 l0 = *(const uint2*)(sAl + (row + g) * 96 + ko);
                uint2 l1 = *(const uint2*)(sAl + (row + g + 8) * 96 + ko);
                uint32_t ahf[4] = { h0.x, h1.x, h0.y, h1.y };
                uint32_t alf[4] = { l0.x, l1.x, l0.y, l1.y };
                #pragma unroll
                for (int j = 0; j < 4; j++) {
                    uint32_t bhr[2] = { bh[j].x, bh[j].y };
                    uint32_t blr[2] = { bl[j].x, bl[j].y };
                    mma_bf16(acc[i][j], ahf, bhr);   // hi*hi
                    mma_bf16(acc[i][j], ahf, blr);   // hi*lo
                    mma_bf16(acc[i][j], alf, bhr);   // lo*hi
                }
            }
        }
        __syncthreads();
    }

    // ---- epilogue ----
    float sc = 0.f;
    if (mode == 1) sc = -0.5f * scale[bz];
    else if (mode == 2) sc = scale[bz];
    const float* D = (mode == 1) ? (Dg + (size_t)bz * sCb) : nullptr;
    const float inv_nm1 = 1.f / (float)(S_ - 1);

    #pragma unroll
    for (int i = 0; i < 4; i++) {
        #pragma unroll
        for (int j = 0; j < 4; j++) {
            int r0 = m0 + warp_m + i * 16 + g;
            int c0 = n0 + warp_n + j * 8 + 2 * tg;
            #pragma unroll
            for (int half = 0; half < 2; half++) {
                int r = r0 + half * 8;
                float v0 = acc[i][j][half * 2 + 0];
                float v1 = acc[i][j][half * 2 + 1];
                size_t off = (size_t)r * N + c0;
                float2 o;
                if (mode == 0) {
                    o.x = v0; o.y = v1;
                } else if (mode == 1) {
                    o.x = 1.5f * D[off] + sc * v0;
                    o.y = 1.5f * D[off + 1] + sc * v1;
                } else if (mode == 2) {
                    o.x = sc * v0; o.y = sc * v1;
                } else {
                    float s0 = v0 * inv_nm1 + ((r == c0)     ? EPS : 0.f);
                    float s1 = v1 * inv_nm1 + ((r == c0 + 1) ? EPS : 0.f);
                    o.x = (1.f - MOMENTUM) * Eg[off] + MOMENTUM * s0;
                    o.y = (1.f - MOMENTUM) * Eg[off + 1] + MOMENTUM * s1;
                }
                *(float2*)(C + off) = o;
                if (TRI && mirror) {
                    C[(size_t)c0 * N + r]       = o.x;
                    C[(size_t)(c0 + 1) * N + r] = o.y;
                }
            }
        }
    }
}

// ---------------- host launcher ----------------
extern "C" void kernel_launch(void* const* d_in, const int* in_sizes, int n_in,
                              void* d_out, int out_size) {
    const float* x  = (const float*)d_in[0];
    const float* rm = (const float*)d_in[1];
    const float* rc = (const float*)d_in[2];
    float* out = (float*)d_out;

    float *xn, *sigma, *P, *Q, *T1, *T2, *mean, *invtr, *rstr;
    cudaGetSymbolAddress((void**)&xn,    g_xn);
    cudaGetSymbolAddress((void**)&sigma, g_sigma);
    cudaGetSymbolAddress((void**)&P,     g_P);
    cudaGetSymbolAddress((void**)&Q,     g_Q);
    cudaGetSymbolAddress((void**)&T1,    g_T1);
    cudaGetSymbolAddress((void**)&T2,    g_T2);
    cudaGetSymbolAddress((void**)&mean,  g_mean);
    cudaGetSymbolAddress((void**)&invtr, g_invtr);
    cudaGetSymbolAddress((void**)&rstr,  g_rstr);

    static bool attr_set = false;
    if (!attr_set) {
        cudaFuncSetAttribute(gemm_bf16x3_kernel<0,0>,
            cudaFuncAttributeMaxDynamicSharedMemorySize, GEMM_SMEM_TOTAL);
        cudaFuncSetAttribute(gemm_bf16x3_kernel<0,1>,
            cudaFuncAttributeMaxDynamicSharedMemorySize, GEMM_SMEM_TOTAL);
        cudaFuncSetAttribute(gemm_bf16x3_kernel<1,1>,
            cudaFuncAttributeMaxDynamicSharedMemorySize, GEMM_SMEM_TOTAL);
        attr_set = true;
    }

    const size_t FF = (size_t)F_ * F_;
    const size_t SF = (size_t)S_ * F_;

    // 1. blended mean
    mean_kernel<<<B_, F_>>>(x, rm, mean);
    // 2. xn = x - m
    xn_kernel<<<(unsigned)((size_t)B_ * SF / 4 / 256), 256>>>(x, mean, xn);
    // 3. sigma = 0.9*rc + 0.1*(xn^T xn /(S-1) + eps*I)  [transA SYRK, triangular]
    gemm_bf16x3_kernel<1,1><<<dim3(10, 1, B_), 256, GEMM_SMEM_TOTAL>>>(
        xn, xn, sigma, nullptr, rc, nullptr, F_, F_, S_, 3, SF, SF, FF);
    // 4. trace
    trace_kernel<<<B_, F_>>>(sigma, invtr, rstr);
    // 5. P1 = 1.5I - 0.5 sigma/tr
    initp_kernel<<<(unsigned)((size_t)B_ * FF / 256), 256>>>(sigma, invtr, P);

    // 6. NS iterations 2..4 (all products symmetric: polynomials in sigma)
    float* Pin = P;
    float* Pout = Q;
    for (int it = 0; it < 3; it++) {
        gemm_bf16x3_kernel<0,1><<<dim3(10, 1, B_), 256, GEMM_SMEM_TOTAL>>>(
            Pin, Pin, T1, nullptr, nullptr, nullptr, F_, F_, F_, 0, FF, FF, FF);
        gemm_bf16x3_kernel<0,1><<<dim3(10, 1, B_), 256, GEMM_SMEM_TOTAL>>>(
            T1, Pin, T2, nullptr, nullptr, nullptr, F_, F_, F_, 0, FF, FF, FF);
        gemm_bf16x3_kernel<0,1><<<dim3(10, 1, B_), 256, GEMM_SMEM_TOTAL>>>(
            T2, sigma, Pout, Pin, nullptr, invtr, F_, F_, F_, 1, FF, FF, FF);
        float* tmp = Pin; Pin = Pout; Pout = tmp;
    }

    // 7. out = (xn @ P) * rsqrt(tr)
    gemm_bf16x3_kernel<0,0><<<dim3(4, 16, B_), 256, GEMM_SMEM_TOTAL>>>(
        xn, Pin, out, nullptr, nullptr, rstr, S_, F_, F_, 2, SF, FF, SF);
}

// round 13
// speedup vs baseline: 1.6864x; 1.4644x over previous
#include <cuda_runtime.h>
#include <cuda_bf16.h>
#include <cstdint>
#include <cstddef>

// Problem constants
#define B_  32
#define S_  2048
#define F_  512
#define MOMENTUM 0.1f
#define EPS 1e-5f

// ---------------- device scratch (static, no allocations) ----------------
__device__ float g_xn   [(size_t)B_ * S_ * F_];   // 128 MB  centered input
__device__ float g_sigma[(size_t)B_ * F_ * F_];
__device__ float g_P    [(size_t)B_ * F_ * F_];
__device__ float g_Q    [(size_t)B_ * F_ * F_];
__device__ float g_T1   [(size_t)B_ * F_ * F_];
__device__ float g_T2   [(size_t)B_ * F_ * F_];
__device__ float g_mean [B_ * F_];
__device__ float g_invtr[B_];
__device__ float g_rstr [B_];

// ---------------- elementwise kernels ----------------
__global__ void mean_kernel(const float* __restrict__ x,
                            const float* __restrict__ rm,
                            float* __restrict__ mean) {
    int b = blockIdx.x;
    int f = threadIdx.x;
    const float* xb = x + (size_t)b * S_ * F_ + f;
    float acc = 0.f;
    #pragma unroll 8
    for (int s = 0; s < S_; s++) acc += xb[(size_t)s * F_];
    mean[b * F_ + f] = (1.f - MOMENTUM) * rm[f] + MOMENTUM * (acc * (1.f / (float)S_));
}

__global__ void xn_kernel(const float* __restrict__ x,
                          const float* __restrict__ mean,
                          float* __restrict__ xn) {
    size_t p4 = (size_t)blockIdx.x * blockDim.x + threadIdx.x;
    size_t p  = p4 * 4;
    int b = (int)(p >> 20);            // S*F = 2^20
    int f = (int)(p & (F_ - 1));
    float4 xv = *(const float4*)(x + p);
    float4 mv = *(const float4*)(mean + b * F_ + f);
    float4 o;
    o.x = xv.x - mv.x; o.y = xv.y - mv.y; o.z = xv.z - mv.z; o.w = xv.w - mv.w;
    *(float4*)(xn + p) = o;
}

__global__ void trace_kernel(const float* __restrict__ sigma,
                             float* __restrict__ invtr,
                             float* __restrict__ rstr) {
    __shared__ float red[512];
    int b = blockIdx.x, t = threadIdx.x;
    red[t] = sigma[(size_t)b * F_ * F_ + (size_t)t * (F_ + 1)];
    __syncthreads();
    for (int s = 256; s > 0; s >>= 1) {
        if (t < s) red[t] += red[t + s];
        __syncthreads();
    }
    if (t == 0) {
        float tr = red[0];
        invtr[b] = 1.f / tr;
        rstr[b]  = 1.f / sqrtf(tr);
    }
}

__global__ void initp_kernel(const float* __restrict__ sigma,
                             const float* __restrict__ invtr,
                             float* __restrict__ P) {
    size_t idx = (size_t)blockIdx.x * blockDim.x + threadIdx.x;
    int b = (int)(idx >> 18);
    int r = (int)((idx >> 9) & (F_ - 1));
    int c = (int)(idx & (F_ - 1));
    float v = -0.5f * invtr[b] * sigma[idx];
    if (r == c) v += 1.5f;
    P[idx] = v;
}

// ---------------- helpers ----------------
__device__ __forceinline__ void cp_async16(void* smem_dst, const void* gmem_src) {
    uint32_t s = (uint32_t)__cvta_generic_to_shared(smem_dst);
    asm volatile("cp.async.cg.shared.global [%0], [%1], 16;\n" :: "r"(s), "l"(gmem_src));
}
#define CP_COMMIT asm volatile("cp.async.commit_group;" ::: "memory")
#define CP_WAIT0  asm volatile("cp.async.wait_group 0;"  ::: "memory")

// split fp32 pair into packed bf16 hi / bf16 lo (x -> lower 16 bits)
__device__ __forceinline__ void split2_bf16(float x, float y, uint32_t& h, uint32_t& l) {
    __nv_bfloat16 hx = __float2bfloat16_rn(x);
    __nv_bfloat16 hy = __float2bfloat16_rn(y);
    float rx = x - __bfloat162float(hx);
    float ry = y - __bfloat162float(hy);
    __nv_bfloat16 lx = __float2bfloat16_rn(rx);
    __nv_bfloat16 ly = __float2bfloat16_rn(ry);
    __nv_bfloat162 hp = __halves2bfloat162(hx, hy);
    __nv_bfloat162 lp = __halves2bfloat162(lx, ly);
    h = *(uint32_t*)&hp;
    l = *(uint32_t*)&lp;
}

__device__ __forceinline__ void mma_bf16(float* c, const uint32_t* a, const uint32_t* b) {
    asm volatile(
        "mma.sync.aligned.m16n8k16.row.col.f32.bf16.bf16.f32 "
        "{%0,%1,%2,%3}, {%4,%5,%6,%7}, {%8,%9}, {%0,%1,%2,%3};"
        : "+f"(c[0]), "+f"(c[1]), "+f"(c[2]), "+f"(c[3])
        : "r"(a[0]), "r"(a[1]), "r"(a[2]), "r"(a[3]), "r"(b[0]), "r"(b[1]));
}

// ---------------- bf16x3 tensor-core GEMM ----------------
// Same pipeline and smem layouts as the 1959us kernel, with ONE change:
// single fp32 stage + single bf16 stage -> 76 KB smem -> 2 CTAs/SM.
// cp.async for chunk c+1 is issued after convert(c) has finished reading the
// fp32 stage, so the copy overlaps mainloop(c).
// mode 0: C = AB
// mode 1: C = 1.5*D - 0.5*scale[b]*AB
// mode 2: C = scale[b]*AB
// mode 3: C = 0.9*E + 0.1*(AB/(S-1) + eps*I)   (E has no batch stride)
//
// fp32 stage: A [128][36] (or [32][132] transA), B [32][132]. 36864 B.
// bf16 arrays: Ah/Al/Bh/Bl each [128 rows][32 k] stride 40 bf16 = 10240 B.
#define STG_FP32_B 36864
#define OFF_BF     STG_FP32_B                 // 36864
#define BF_STAGE_B 40960
#define GEMM_SMEM_TOTAL (OFF_BF + BF_STAGE_B) // 77824

template<int TRANSA, int TRI>
__global__ __launch_bounds__(256, 2) void gemm_bf16x3_kernel(
        const float* __restrict__ Ag, const float* __restrict__ Bg,
        float* __restrict__ Cg, const float* __restrict__ Dg,
        const float* __restrict__ Eg, const float* __restrict__ scale,
        int M, int N, int K, int mode,
        size_t sAb, size_t sBb, size_t sCb) {
    extern __shared__ char smem[];

    int bz = blockIdx.z;
    const float* A = Ag + (size_t)bz * sAb;
    const float* Bm = Bg + (size_t)bz * sBb;
    float* C = Cg + (size_t)bz * sCb;

    int m0, n0;
    bool mirror = false;
    if (TRI) {
        int t = blockIdx.x;   // 0..9
        int bi = (t < 4) ? 0 : (t < 7) ? 1 : (t < 9) ? 2 : 3;
        int start = (bi == 0) ? 0 : (bi == 1) ? 4 : (bi == 2) ? 7 : 9;
        int bj = bi + (t - start);
        m0 = bi * 128; n0 = bj * 128;
        mirror = (bi != bj);
    } else {
        m0 = blockIdx.y * 128;
        n0 = blockIdx.x * 128;
    }

    int tid  = threadIdx.x;
    int lane = tid & 31;
    int wid  = tid >> 5;
    int warp_m = (wid >> 2) * 64;     // 0 or 64
    int warp_n = (wid & 3) * 32;      // 0,32,64,96
    int g  = lane >> 2;               // 0..7
    int tg = lane & 3;                // 0..3

    float acc[4][4][4];
    #pragma unroll
    for (int i = 0; i < 4; i++)
        #pragma unroll
        for (int j = 0; j < 4; j++)
            #pragma unroll
            for (int q = 0; q < 4; q++) acc[i][j][q] = 0.f;

    // ---- cp.async staging of fp32 tiles (single stage) ----
    auto prefetch = [&](int k0) {
        float* sA = (float*)smem;
        float* sB = sA + 4608;
        if (!TRANSA) {
            #pragma unroll
            for (int p = 0; p < 4; p++) {
                int c = tid + p * 256;
                int m = c >> 3;
                int kc = (c & 7) * 4;
                cp_async16(sA + m * 36 + kc, A + (size_t)(m0 + m) * K + k0 + kc);
            }
        } else {
            #pragma unroll
            for (int p = 0; p < 4; p++) {
                int c = tid + p * 256;
                int k = c >> 5;
                int mc = (c & 31) * 4;
                cp_async16(sA + k * 132 + mc, A + (size_t)(k0 + k) * M + m0 + mc);
            }
        }
        #pragma unroll
        for (int p = 0; p < 4; p++) {
            int c = tid + p * 256;
            int k = c >> 5;
            int nc = (c & 31) * 4;
            cp_async16(sB + k * 132 + nc, Bm + (size_t)(k0 + k) * N + n0 + nc);
        }
    };

    prefetch(0);
    CP_COMMIT;

    const int NC = K >> 5;
    const int mrow = tid >> 1;             // 0..127
    const int ks   = (tid & 1) * 16;       // 0 or 16

    for (int c = 0; c < NC; c++) {
        CP_WAIT0;
        __syncthreads();   // fp32 stage ready; previous mainloop done

        // ---- convert: fp32 stage -> packed bf16 hi/lo (B transposed) ----
        {
            const float* fA = (const float*)smem;
            const float* fB = fA + 4608;
            char* bf = smem + OFF_BF;
            uint32_t* dAh = (uint32_t*)(bf +      0 + (size_t)(mrow * 40 + ks) * 2);
            uint32_t* dAl = (uint32_t*)(bf +  10240 + (size_t)(mrow * 40 + ks) * 2);
            uint32_t* dBh = (uint32_t*)(bf +  20480 + (size_t)(mrow * 40 + ks) * 2);
            uint32_t* dBl = (uint32_t*)(bf +  30720 + (size_t)(mrow * 40 + ks) * 2);
            if (!TRANSA) {
                const float* s = fA + mrow * 36 + ks;
                #pragma unroll
                for (int u = 0; u < 4; u++) {
                    float4 v = *(const float4*)(s + 4 * u);
                    uint32_t h0, l0, h1, l1;
                    split2_bf16(v.x, v.y, h0, l0);
                    split2_bf16(v.z, v.w, h1, l1);
                    dAh[2 * u] = h0; dAh[2 * u + 1] = h1;
                    dAl[2 * u] = l0; dAl[2 * u + 1] = l1;
                }
            } else {
                const float* s = fA + mrow;      // [k][132]
                #pragma unroll
                for (int u = 0; u < 8; u++) {
                    float v0 = s[(ks + 2 * u) * 132];
                    float v1 = s[(ks + 2 * u + 1) * 132];
                    uint32_t h, l;
                    split2_bf16(v0, v1, h, l);
                    dAh[u] = h; dAl[u] = l;
                }
            }
            // B transpose convert
            const float* s = fB + mrow;          // [k][132], col = mrow
            #pragma unroll
            for (int u = 0; u < 8; u++) {
                float v0 = s[(ks + 2 * u) * 132];
                float v1 = s[(ks + 2 * u + 1) * 132];
                uint32_t h, l;
                split2_bf16(v0, v1, h, l);
                dBh[u] = h; dBl[u] = l;
            }
        }
        __syncthreads();   // all convert reads of fp32 stage complete

        // issue next chunk's copies; they overlap the mainloop below
        if (c + 1 < NC) {
            prefetch((c + 1) * 32);
            CP_COMMIT;
        }

        // ---- compute: 2 k-steps of 16 ----
        const char* bf = smem + OFF_BF;
        const char* Ah = bf;
        const char* Al = bf + 10240;
        const char* Bh = bf + 20480;
        const char* Bl = bf + 30720;
        #pragma unroll
        for (int kk = 0; kk < 32; kk += 16) {
            int kf = kk + 2 * tg;
            uint32_t bh[4][2], bl[4][2];
            #pragma unroll
            for (int j = 0; j < 4; j++) {
                int col = warp_n + j * 8 + g;
                bh[j][0] = *(const uint32_t*)(Bh + (size_t)(col * 40 + kf) * 2);
                bh[j][1] = *(const uint32_t*)(Bh + (size_t)(col * 40 + kf + 8) * 2);
                bl[j][0] = *(const uint32_t*)(Bl + (size_t)(col * 40 + kf) * 2);
                bl[j][1] = *(const uint32_t*)(Bl + (size_t)(col * 40 + kf + 8) * 2);
            }
            #pragma unroll
            for (int i = 0; i < 4; i++) {
                int row = warp_m + i * 16;
                uint32_t ah[4], al[4];
                ah[0] = *(const uint32_t*)(Ah + (size_t)((row + g) * 40 + kf) * 2);
                ah[1] = *(const uint32_t*)(Ah + (size_t)((row + g + 8) * 40 + kf) * 2);
                ah[2] = *(const uint32_t*)(Ah + (size_t)((row + g) * 40 + kf + 8) * 2);
                ah[3] = *(const uint32_t*)(Ah + (size_t)((row + g + 8) * 40 + kf + 8) * 2);
                al[0] = *(const uint32_t*)(Al + (size_t)((row + g) * 40 + kf) * 2);
                al[1] = *(const uint32_t*)(Al + (size_t)((row + g + 8) * 40 + kf) * 2);
                al[2] = *(const uint32_t*)(Al + (size_t)((row + g) * 40 + kf + 8) * 2);
                al[3] = *(const uint32_t*)(Al + (size_t)((row + g + 8) * 40 + kf + 8) * 2);
                #pragma unroll
                for (int j = 0; j < 4; j++) {
                    mma_bf16(acc[i][j], ah, bh[j]);   // hi*hi
                    mma_bf16(acc[i][j], ah, bl[j]);   // hi*lo
                    mma_bf16(acc[i][j], al, bh[j]);   // lo*hi
                }
            }
        }
    }

    // ---- epilogue ----
    float sc = 0.f;
    if (mode == 1) sc = -0.5f * scale[bz];
    else if (mode == 2) sc = scale[bz];
    const float* D = (mode == 1) ? (Dg + (size_t)bz * sCb) : nullptr;
    const float inv_nm1 = 1.f / (float)(S_ - 1);

    #pragma unroll
    for (int i = 0; i < 4; i++) {
        #pragma unroll
        for (int j = 0; j < 4; j++) {
            int r0 = m0 + warp_m + i * 16 + g;
            int c0 = n0 + warp_n + j * 8 + 2 * tg;
            #pragma unroll
            for (int half = 0; half < 2; half++) {
                int r = r0 + half * 8;
                float v0 = acc[i][j][half * 2 + 0];
                float v1 = acc[i][j][half * 2 + 1];
                size_t off = (size_t)r * N + c0;
                float2 o;
                if (mode == 0) {
                    o.x = v0; o.y = v1;
                } else if (mode == 1) {
                    o.x = 1.5f * D[off] + sc * v0;
                    o.y = 1.5f * D[off + 1] + sc * v1;
                } else if (mode == 2) {
                    o.x = sc * v0; o.y = sc * v1;
                } else {
                    float s0 = v0 * inv_nm1 + ((r == c0)     ? EPS : 0.f);
                    float s1 = v1 * inv_nm1 + ((r == c0 + 1) ? EPS : 0.f);
                    o.x = (1.f - MOMENTUM) * Eg[off] + MOMENTUM * s0;
                    o.y = (1.f - MOMENTUM) * Eg[off + 1] + MOMENTUM * s1;
                }
                *(float2*)(C + off) = o;
                if (TRI && mirror) {
                    C[(size_t)c0 * N + r]       = o.x;
                    C[(size_t)(c0 + 1) * N + r] = o.y;
                }
            }
        }
    }
}

// ---------------- host launcher ----------------
extern "C" void kernel_launch(void* const* d_in, const int* in_sizes, int n_in,
                              void* d_out, int out_size) {
    const float* x  = (const float*)d_in[0];
    const float* rm = (const float*)d_in[1];
    const float* rc = (const float*)d_in[2];
    float* out = (float*)d_out;

    float *xn, *sigma, *P, *Q, *T1, *T2, *mean, *invtr, *rstr;
    cudaGetSymbolAddress((void**)&xn,    g_xn);
    cudaGetSymbolAddress((void**)&sigma, g_sigma);
    cudaGetSymbolAddress((void**)&P,     g_P);
    cudaGetSymbolAddress((void**)&Q,     g_Q);
    cudaGetSymbolAddress((void**)&T1,    g_T1);
    cudaGetSymbolAddress((void**)&T2,    g_T2);
    cudaGetSymbolAddress((void**)&mean,  g_mean);
    cudaGetSymbolAddress((void**)&invtr, g_invtr);
    cudaGetSymbolAddress((void**)&rstr,  g_rstr);

    static bool attr_set = false;
    if (!attr_set) {
        cudaFuncSetAttribute(gemm_bf16x3_kernel<0,0>,
            cudaFuncAttributeMaxDynamicSharedMemorySize, GEMM_SMEM_TOTAL);
        cudaFuncSetAttribute(gemm_bf16x3_kernel<0,1>,
            cudaFuncAttributeMaxDynamicSharedMemorySize, GEMM_SMEM_TOTAL);
        cudaFuncSetAttribute(gemm_bf16x3_kernel<1,1>,
            cudaFuncAttributeMaxDynamicSharedMemorySize, GEMM_SMEM_TOTAL);
        attr_set = true;
    }

    const size_t FF = (size_t)F_ * F_;
    const size_t SF = (size_t)S_ * F_;

    // 1. blended mean
    mean_kernel<<<B_, F_>>>(x, rm, mean);
    // 2. xn = x - m
    xn_kernel<<<(unsigned)((size_t)B_ * SF / 4 / 256), 256>>>(x, mean, xn);
    // 3. sigma = 0.9*rc + 0.1*(xn^T xn /(S-1) + eps*I)  [transA SYRK, triangular]
    gemm_bf16x3_kernel<1,1><<<dim3(10, 1, B_), 256, GEMM_SMEM_TOTAL>>>(
        xn, xn, sigma, nullptr, rc, nullptr, F_, F_, S_, 3, SF, SF, FF);
    // 4. trace
    trace_kernel<<<B_, F_>>>(sigma, invtr, rstr);
    // 5. P1 = 1.5I - 0.5 sigma/tr
    initp_kernel<<<(unsigned)((size_t)B_ * FF / 256), 256>>>(sigma, invtr, P);

    // 6. NS iterations 2..4 (all products symmetric: polynomials in sigma)
    float* Pin = P;
    float* Pout = Q;
    for (int it = 0; it < 3; it++) {
        gemm_bf16x3_kernel<0,1><<<dim3(10, 1, B_), 256, GEMM_SMEM_TOTAL>>>(
            Pin, Pin, T1, nullptr, nullptr, nullptr, F_, F_, F_, 0, FF, FF, FF);
        gemm_bf16x3_kernel<0,1><<<dim3(10, 1, B_), 256, GEMM_SMEM_TOTAL>>>(
            T1, Pin, T2, nullptr, nullptr, nullptr, F_, F_, F_, 0, FF, FF, FF);
        gemm_bf16x3_kernel<0,1><<<dim3(10, 1, B_), 256, GEMM_SMEM_TOTAL>>>(
            T2, sigma, Pout, Pin, nullptr, invtr, F_, F_, F_, 1, FF, FF, FF);
        float* tmp = Pin; Pin = Pout; Pout = tmp;
    }

    // 7. out = (xn @ P) * rsqrt(tr)
    gemm_bf16x3_kernel<0,0><<<dim3(4, 16, B_), 256, GEMM_SMEM_TOTAL>>>(
        xn, Pin, out, nullptr, nullptr, rstr, S_, F_, F_, 2, SF, FF, SF);
}